// round 15
// baseline (speedup 1.0000x reference)
#include <cuda_runtime.h>
#include <cuda_bf16.h>
#include <cstdint>

// ---------------------------------------------------------------------------
// Transformer-XL masked MHA. S=1024, P=1024, J=2048, B=2, E=1024, H=16, I=64.
// All GEMM operands pre-converted to bf16 (hi, and lo where fp32-grade
// accuracy is needed); GEMMs are pure-bf16 cp.async pipelines.
// Softmax-side: 1-term. Output-side (V-proj, PV, out-proj): 3-term split.
// ---------------------------------------------------------------------------

constexpr int S_   = 1024;
constexpr int P_   = 1024;
constexpr int B_   = 2;
constexpr int E_   = 1024;
constexpr int H_   = 16;
constexpr int I_   = 64;
constexpr int J_   = 2048;
constexpr int HI_  = 1024;
constexpr int JB_  = J_ * B_;
constexpr float SCALE_ = 0.125f;
constexpr float EPS_   = 1e-5f;

// ------------------------- scratch (device globals) ------------------------
__device__ __nv_bfloat16 g_iwh [(size_t)JB_*E_];       // concat(mem,x) hi
__device__ __nv_bfloat16 g_iwl [(size_t)JB_*E_];       // concat(mem,x) lo
__device__ __nv_bfloat16 g_relh[(size_t)J_*E_];
__device__ __nv_bfloat16 g_wkh [(size_t)HI_*E_];
__device__ __nv_bfloat16 g_wvh [(size_t)HI_*E_];
__device__ __nv_bfloat16 g_wvl [(size_t)HI_*E_];
__device__ __nv_bfloat16 g_wqh [(size_t)HI_*E_];
__device__ __nv_bfloat16 g_wph [(size_t)HI_*E_];
__device__ __nv_bfloat16 g_woh [(size_t)E_*HI_];
__device__ __nv_bfloat16 g_wol [(size_t)E_*HI_];

__device__ __nv_bfloat16 g_Khi [(size_t)B_*H_*J_*I_];  // [bh][j][i]
__device__ __nv_bfloat16 g_Vthi[(size_t)B_*H_*I_*J_];  // [bh][i][j]
__device__ __nv_bfloat16 g_Vtlo[(size_t)B_*H_*I_*J_];
__device__ __nv_bfloat16 g_quhi[(size_t)B_*H_*S_*I_];
__device__ __nv_bfloat16 g_qvh [(size_t)B_*H_*S_*I_];
__device__ __nv_bfloat16 g_posh[(size_t)H_*J_*I_];
__device__ __nv_bfloat16 g_PD  [(size_t)B_*H_*S_*J_];  // pre-shifted
__device__ __nv_bfloat16 g_ctxh[(size_t)S_*B_*HI_];
__device__ __nv_bfloat16 g_ctxl[(size_t)S_*B_*HI_];
__device__ float g_proj[(size_t)S_*B_*E_];

// ------------------------------ helpers ------------------------------------
__device__ __forceinline__ void split1(float x, __nv_bfloat16& h, __nv_bfloat16& l) {
    h = __float2bfloat16(x);
    l = __float2bfloat16(x - __bfloat162float(h));
}
__device__ __forceinline__ void split2(float x, float y,
                                       uint32_t& hi, uint32_t& lo) {
    __nv_bfloat162 h = __floats2bfloat162_rn(x, y);
    __nv_bfloat162 l = __floats2bfloat162_rn(x - __bfloat162float(h.x),
                                             y - __bfloat162float(h.y));
    hi = *(const uint32_t*)&h;
    lo = *(const uint32_t*)&l;
}
__device__ __forceinline__ uint32_t packbf2(float x, float y) {
    __nv_bfloat162 t = __floats2bfloat162_rn(x, y);
    return *(const uint32_t*)&t;
}
__device__ __forceinline__ uint32_t pack2h(__nv_bfloat16 a, __nv_bfloat16 b) {
    __nv_bfloat162 t; t.x = a; t.y = b;
    return *(const uint32_t*)&t;
}
__device__ __forceinline__ void mma_bf16(float* d, const uint32_t* a,
                                         const uint32_t* b) {
    asm volatile(
        "mma.sync.aligned.m16n8k16.row.col.f32.bf16.bf16.f32 "
        "{%0,%1,%2,%3}, {%4,%5,%6,%7}, {%8,%9}, {%0,%1,%2,%3};"
        : "+f"(d[0]), "+f"(d[1]), "+f"(d[2]), "+f"(d[3])
        : "r"(a[0]), "r"(a[1]), "r"(a[2]), "r"(a[3]), "r"(b[0]), "r"(b[1]));
}

#define CP_ASYNC16(dst_u32, src_ptr) \
    asm volatile("cp.async.cg.shared.global [%0], [%1], 16;" \
                 :: "r"(dst_u32), "l"(src_ptr) : "memory")
#define CP_COMMIT() asm volatile("cp.async.commit_group;" ::: "memory")
#define CP_WAIT1()  asm volatile("cp.async.wait_group 1;" ::: "memory")
#define CP_WAIT0()  asm volatile("cp.async.wait_group 0;" ::: "memory")

// ------------------------ conversion prepass kernels -----------------------
__global__ void __launch_bounds__(256)
conv_hi(const float* __restrict__ src, __nv_bfloat16* __restrict__ dst, int n4) {
    int i = blockIdx.x * 256 + threadIdx.x;
    if (i < n4) {
        float4 v = ((const float4*)src)[i];
        *(uint2*)&dst[(size_t)i * 4] =
            make_uint2(packbf2(v.x, v.y), packbf2(v.z, v.w));
    }
}
__global__ void __launch_bounds__(256)
conv_hilo(const float* __restrict__ src, __nv_bfloat16* __restrict__ dh,
          __nv_bfloat16* __restrict__ dl, int n4) {
    int i = blockIdx.x * 256 + threadIdx.x;
    if (i < n4) {
        float4 v = ((const float4*)src)[i];
        uint32_t h0, l0, h1, l1;
        split2(v.x, v.y, h0, l0);
        split2(v.z, v.w, h1, l1);
        *(uint2*)&dh[(size_t)i * 4] = make_uint2(h0, h1);
        *(uint2*)&dl[(size_t)i * 4] = make_uint2(l0, l1);
    }
}

// ------------------------------- C functors --------------------------------
struct CStoreK {
    __device__ __forceinline__ void operator()(int m, int n, float c) const {
        int j = m / B_, b = m % B_;
        int hh = n >> 6, i = n & 63;
        g_Khi[(((size_t)(b*H_ + hh))*J_ + j)*I_ + i] = __float2bfloat16(c);
    }
};
struct CStoreV {
    __device__ __forceinline__ void operator()(int m, int n, float c) const {
        int j = m / B_, b = m % B_;
        int hh = n >> 6, i = n & 63;
        __nv_bfloat16 h, l;
        split1(c, h, l);
        size_t o = (((size_t)(b*H_ + hh))*I_ + i)*J_ + j;  // transposed
        g_Vthi[o] = h; g_Vtlo[o] = l;
    }
};
struct CStoreQ {
    const float* u; const float* v;
    __device__ __forceinline__ void operator()(int m, int n, float c) const {
        int s = m / B_, b = m % B_;
        int hh = n >> 6, i = n & 63;
        size_t o = (((size_t)(b*H_ + hh))*S_ + s)*I_ + i;
        g_quhi[o] = __float2bfloat16(c + u[n]);
        g_qvh[o]  = __float2bfloat16(c + v[n]);
    }
};
struct CStorePos {
    __device__ __forceinline__ void operator()(int m, int n, float c) const {
        int hh = n >> 6, i = n & 63;
        g_posh[((size_t)hh*J_ + m)*I_ + i] = __float2bfloat16(c);
    }
};
struct CStoreProj {
    const float* x;
    __device__ __forceinline__ void operator()(int m, int n, float c) const {
        g_proj[(size_t)m*E_ + n] = c + x[(size_t)m*E_ + n];
    }
};

// ------------------- pure-bf16 cp.async GEMM (1t / 3t) ---------------------
// C[m,n] = sum_k A[m,k]*B[n,k]; operands bf16 row-major, stride K.
// 128x128 tile, BK=32, double-buffered cp.async. GROW=40 (80B row stride).
constexpr int GROW = 40;
constexpr int GTS  = 128 * GROW;                 // elems per array per stage
template<bool SP> constexpr int gemm_smem() { return 2 * (SP?4:2) * GTS * 2; }

template<bool SP, class CS>
__global__ void __launch_bounds__(256)
gemm_bf(const __nv_bfloat16* __restrict__ Ah, const __nv_bfloat16* __restrict__ Al,
        const __nv_bfloat16* __restrict__ Bh, const __nv_bfloat16* __restrict__ Bl,
        CS cstore, int K) {
    constexpr int NA = SP ? 4 : 2;
    extern __shared__ __nv_bfloat16 gsm[];

    const int tid  = threadIdx.x;
    const int wid  = tid >> 5;
    const int lane = tid & 31;
    const int gid  = lane >> 2;
    const int tig  = lane & 3;
    const int wm   = wid >> 2;
    const int wn   = wid & 3;
    const int m0   = blockIdx.y * 128;
    const int n0   = blockIdx.x * 128;

    const int frow = tid >> 1;               // 0..127
    const int fb   = (tid & 1) * 32;         // byte offset within 64B row

    auto issue = [&](int st, int k0) {
        __nv_bfloat16* buf = gsm + st * NA * GTS;
        const char* sa = (const char*)(Ah + (size_t)(m0 + frow) * K + k0) + fb;
        uint32_t da = (uint32_t)__cvta_generic_to_shared(&buf[frow * GROW]) + fb;
        CP_ASYNC16(da, sa); CP_ASYNC16(da + 16, sa + 16);
        const char* sb = (const char*)(Bh + (size_t)(n0 + frow) * K + k0) + fb;
        uint32_t db = (uint32_t)__cvta_generic_to_shared(
            &buf[(SP ? 2 : 1) * GTS + frow * GROW]) + fb;
        CP_ASYNC16(db, sb); CP_ASYNC16(db + 16, sb + 16);
        if constexpr (SP) {
            const char* sal = (const char*)(Al + (size_t)(m0 + frow) * K + k0) + fb;
            uint32_t dal = (uint32_t)__cvta_generic_to_shared(
                &buf[GTS + frow * GROW]) + fb;
            CP_ASYNC16(dal, sal); CP_ASYNC16(dal + 16, sal + 16);
            const char* sbl = (const char*)(Bl + (size_t)(n0 + frow) * K + k0) + fb;
            uint32_t dbl = (uint32_t)__cvta_generic_to_shared(
                &buf[3 * GTS + frow * GROW]) + fb;
            CP_ASYNC16(dbl, sbl); CP_ASYNC16(dbl + 16, sbl + 16);
        }
    };

    float c[4][4][4];
#pragma unroll
    for (int mt = 0; mt < 4; mt++)
#pragma unroll
        for (int nt = 0; nt < 4; nt++)
#pragma unroll
            for (int r = 0; r < 4; r++) c[mt][nt][r] = 0.f;

    issue(0, 0); CP_COMMIT();
    const int nc = K >> 5;
    for (int ch = 0; ch < nc; ch++) {
        if (ch + 1 < nc) { issue((ch + 1) & 1, (ch + 1) * 32); CP_COMMIT(); CP_WAIT1(); }
        else             { CP_WAIT0(); }
        __syncthreads();

        const __nv_bfloat16* buf = gsm + (ch & 1) * NA * GTS;
        const __nv_bfloat16* sAh = buf;
        const __nv_bfloat16* sAl = buf + GTS;
        const __nv_bfloat16* sBh = buf + (SP ? 2 : 1) * GTS;
        const __nv_bfloat16* sBl = buf + 3 * GTS;

#pragma unroll
        for (int ks = 0; ks < 2; ks++) {
            const int kk = ks * 16 + tig * 2;
            uint32_t ah[4][4], al[4][4];
#pragma unroll
            for (int mt = 0; mt < 4; mt++) {
                const int m = wm * 64 + mt * 16 + gid;
                ah[mt][0] = *(const uint32_t*)&sAh[m * GROW + kk];
                ah[mt][1] = *(const uint32_t*)&sAh[(m + 8) * GROW + kk];
                ah[mt][2] = *(const uint32_t*)&sAh[m * GROW + kk + 8];
                ah[mt][3] = *(const uint32_t*)&sAh[(m + 8) * GROW + kk + 8];
                if constexpr (SP) {
                    al[mt][0] = *(const uint32_t*)&sAl[m * GROW + kk];
                    al[mt][1] = *(const uint32_t*)&sAl[(m + 8) * GROW + kk];
                    al[mt][2] = *(const uint32_t*)&sAl[m * GROW + kk + 8];
                    al[mt][3] = *(const uint32_t*)&sAl[(m + 8) * GROW + kk + 8];
                }
            }
#pragma unroll
            for (int nt = 0; nt < 4; nt++) {
                const int n = wn * 32 + nt * 8 + gid;
                uint32_t bh[2], bl[2];
                bh[0] = *(const uint32_t*)&sBh[n * GROW + kk];
                bh[1] = *(const uint32_t*)&sBh[n * GROW + kk + 8];
                if constexpr (SP) {
                    bl[0] = *(const uint32_t*)&sBl[n * GROW + kk];
                    bl[1] = *(const uint32_t*)&sBl[n * GROW + kk + 8];
                }
#pragma unroll
                for (int mt = 0; mt < 4; mt++) {
                    mma_bf16(c[mt][nt], ah[mt], bh);
                    if constexpr (SP) {
                        mma_bf16(c[mt][nt], ah[mt], bl);
                        mma_bf16(c[mt][nt], al[mt], bh);
                    }
                }
            }
        }
        __syncthreads();
    }

#pragma unroll
    for (int mt = 0; mt < 4; mt++) {
        const int gm = m0 + wm * 64 + mt * 16 + gid;
#pragma unroll
        for (int nt = 0; nt < 4; nt++) {
            const int gn = n0 + wn * 32 + nt * 8 + tig * 2;
            cstore(gm,     gn,     c[mt][nt][0]);
            cstore(gm,     gn + 1, c[mt][nt][1]);
            cstore(gm + 8, gn,     c[mt][nt][2]);
            cstore(gm + 8, gn + 1, c[mt][nt][3]);
        }
    }
}

// ----------------------- PD kernel (pure bf16, K=64) -----------------------
constexpr int PDW = 36;
constexpr int PD_SMEM = (128 + 64 + 64 + 128) * 72 * 2;   // 55296 B

__global__ void __launch_bounds__(256) pd_kernel() {
    extern __shared__ __nv_bfloat16 psm[];
    __nv_bfloat16* sA   = psm;                // [128][72]
    __nv_bfloat16* sB0  = sA  + 128 * 72;     // [64][72]
    __nv_bfloat16* sB1  = sB0 + 64 * 72;
    __nv_bfloat16* sOut = sB1 + 64 * 72;      // [128][72]

    const int tid  = threadIdx.x;
    const int wq   = tid >> 5;
    const int lane = tid & 31;
    const int gid  = lane >> 2;
    const int tig  = lane & 3;
    const int m0   = blockIdx.y * 128;
    const int ng   = blockIdx.x * 256;
    const int bh   = blockIdx.z;

    int need = 833 - m0 - ng;
    int ns_min = (need <= 0) ? 0 : ((need + 63) >> 6);
    if (ns_min > 3) return;

    const int arow = tid >> 1;
    const int aw   = (tid & 1) * 16;
    const int brow = tid >> 2;
    const int bw   = (tid & 3) * 8;

    auto issueA = [&]() {
        const char* src = (const char*)((const uint32_t*)
            (g_qvh + ((size_t)bh * S_ + m0 + arow) * I_) + aw);
        uint32_t dst = (uint32_t)__cvta_generic_to_shared(
            (uint32_t*)&sA[arow * 72] + aw);
        CP_ASYNC16(dst,      src);
        CP_ASYNC16(dst + 16, src + 16);
        CP_ASYNC16(dst + 32, src + 32);
        CP_ASYNC16(dst + 48, src + 48);
    };
    auto issueB = [&](int ns, __nv_bfloat16* buf) {
        const int n0 = ng + ns * 64;
        const char* src = (const char*)((const uint32_t*)
            (g_posh + ((size_t)(bh & 15) * J_ + n0 + brow) * I_) + bw);
        uint32_t dst = (uint32_t)__cvta_generic_to_shared(
            (uint32_t*)&buf[brow * 72] + bw);
        CP_ASYNC16(dst,      src);
        CP_ASYNC16(dst + 16, src + 16);
    };

    issueA();
    issueB(ns_min, sB0);
    CP_COMMIT();
    if (ns_min + 1 <= 3) { issueB(ns_min + 1, sB1); CP_COMMIT(); }

    const int r0w = (wq * 16 + gid) * PDW;

    for (int ns = ns_min; ns <= 3; ns++) {
        const int idx = ns - ns_min;
        if (ns + 1 <= 3) CP_WAIT1(); else CP_WAIT0();
        __syncthreads();

        const uint32_t* qa = (const uint32_t*)sA;
        const uint32_t* qb = (const uint32_t*)((idx & 1) ? sB1 : sB0);

        float c[8][4];
#pragma unroll
        for (int nt = 0; nt < 8; nt++)
#pragma unroll
            for (int r = 0; r < 4; r++) c[nt][r] = 0.f;

#pragma unroll
        for (int ks = 0; ks < 4; ks++) {
            const int w = ks * 8 + tig;
            uint32_t a[4];
            a[0] = qa[r0w + w];
            a[1] = qa[r0w + 8 * PDW + w];
            a[2] = qa[r0w + w + 4];
            a[3] = qa[r0w + 8 * PDW + w + 4];
#pragma unroll
            for (int nt = 0; nt < 8; nt++) {
                const int nw = (nt * 8 + gid) * PDW;
                uint32_t b2[2] = { qb[nw + w], qb[nw + w + 4] };
                mma_bf16(c[nt], a, b2);
            }
        }
        __syncthreads();
        if (ns + 2 <= 3) { issueB(ns + 2, (idx & 1) ? sB1 : sB0); CP_COMMIT(); }

        {
            const int r0s = (wq * 16 + gid) * 72;
#pragma unroll
            for (int nt = 0; nt < 8; nt++) {
                *(uint32_t*)&sOut[r0s + nt * 8 + tig * 2] =
                    packbf2(c[nt][0], c[nt][1]);
                *(uint32_t*)&sOut[r0s + 8 * 72 + nt * 8 + tig * 2] =
                    packbf2(c[nt][2], c[nt][3]);
            }
        }
        __syncwarp();

        const int n0s = ng + ns * 64;
#pragma unroll
        for (int it = 0; it < 16; it++) {
            const int r  = wq * 16 + it;
            const int gm = m0 + r;
            const int jr = n0s + gm - 1023;
            if (jr + 63 < 0) continue;
            const uint32_t* srow = (const uint32_t*)&sOut[r * 72];
            __nv_bfloat16* drow = g_PD + ((size_t)bh * S_ + gm) * J_;
            if ((jr & 1) == 0) {
                const int j = jr + lane * 2;
                if (j >= 0) *(uint32_t*)&drow[j] = srow[lane];
            } else {
                if (lane < 31) {
                    const int j = jr + 1 + lane * 2;
                    if (j >= 0) {
                        uint32_t w0 = srow[lane], w1 = srow[lane + 1];
                        *(uint32_t*)&drow[j] = (w0 >> 16) | (w1 << 16);
                    }
                } else {
                    if (jr >= 0)      drow[jr]      = sOut[r * 72];
                    if (jr + 63 >= 0) drow[jr + 63] = sOut[r * 72 + 63];
                }
            }
        }
    }
}

// ---------------------------- flash attention (MMA) ------------------------
constexpr int FPAD = 72;
constexpr int FLASH_SMEM = (128 + 64 + 128) * FPAD * 2;  // 46080 B

__global__ void __launch_bounds__(256) flash_mma() {
    extern __shared__ __nv_bfloat16 fsm[];
    __nv_bfloat16* sQh = fsm;                    // [s][i] 128x72
    __nv_bfloat16* sKh = sQh + 128 * FPAD;       // [j][i] 64x72
    __nv_bfloat16* sVh = sKh + 64 * FPAD;        // [i][j] 64x72
    __nv_bfloat16* sVl = sVh + 64 * FPAD;

    const int tid  = threadIdx.x;
    const int wq   = tid >> 5;
    const int lane = tid & 31;
    const int gid  = lane >> 2;
    const int tig  = lane & 3;
    const int s0   = (gridDim.x - 1 - blockIdx.x) * 128;
    const int bh   = blockIdx.y;

    const int s_r0 = s0 + wq * 16 + gid;
    const int s_r1 = s_r0 + 8;

    const int row4 = tid >> 2;
    const int qw   = (tid & 3) * 8;

    auto issueK = [&](int j0) {
        const char* srch = (const char*)((const uint32_t*)
            (g_Khi + (((size_t)bh * J_) + j0 + row4) * I_) + qw);
        uint32_t dh = (uint32_t)__cvta_generic_to_shared(
            (uint32_t*)&sKh[row4 * FPAD] + qw);
        CP_ASYNC16(dh,      srch);
        CP_ASYNC16(dh + 16, srch + 16);
    };
    auto issueV = [&](int j0) {
        const char* srch = (const char*)((const uint32_t*)
            (g_Vthi + ((size_t)bh * I_ + row4) * J_ + j0) + qw);
        const char* srcl = (const char*)((const uint32_t*)
            (g_Vtlo + ((size_t)bh * I_ + row4) * J_ + j0) + qw);
        uint32_t dh = (uint32_t)__cvta_generic_to_shared(
            (uint32_t*)&sVh[row4 * FPAD] + qw);
        uint32_t dl = (uint32_t)__cvta_generic_to_shared(
            (uint32_t*)&sVl[row4 * FPAD] + qw);
        CP_ASYNC16(dh,      srch);
        CP_ASYNC16(dh + 16, srch + 16);
        CP_ASYNC16(dl,      srcl);
        CP_ASYNC16(dl + 16, srcl + 16);
    };

    issueK(0); CP_COMMIT();
    issueV(0); CP_COMMIT();

    {
        const int row  = tid >> 1;
        const int half = (tid & 1) * 16;
        const uint4* srch = (const uint4*)((const uint32_t*)
            (g_quhi + ((size_t)bh * S_ + s0 + row) * I_) + half);
        uint4* dsth = (uint4*)((uint32_t*)&sQh[row * FPAD] + half);
#pragma unroll
        for (int q = 0; q < 4; q++) dsth[q] = srch[q];
    }

    const __nv_bfloat16* PDb = g_PD + (size_t)bh * S_ * J_;

    float m_[2] = {-3.0e38f, -3.0e38f};
    float l_[2] = {0.f, 0.f};
    float o[8][4];
#pragma unroll
    for (int nt = 0; nt < 8; nt++)
#pragma unroll
        for (int r = 0; r < 4; r++) o[nt][r] = 0.f;

    const int ntiles = min(32, s0 / 64 + 18);
    for (int jt = 0; jt < ntiles; jt++) {
        const int j0 = jt * 64;
        const int jn = min(jt + 1, ntiles - 1) * 64;

        CP_WAIT1();
        __syncthreads();

        float sc[8][4];
#pragma unroll
        for (int nt = 0; nt < 8; nt++)
#pragma unroll
            for (int r = 0; r < 4; r++) sc[nt][r] = 0.f;

        const uint32_t* qh32 = (const uint32_t*)sQh;
        const uint32_t* kh32 = (const uint32_t*)sKh;
        const int r0w = (wq * 16 + gid) * (FPAD/2);
        const int r1w = r0w + 8 * (FPAD/2);
#pragma unroll
        for (int ks = 0; ks < 4; ks++) {
            const int w = ks * 8 + tig;
            uint32_t ah[4];
            ah[0] = qh32[r0w + w];     ah[1] = qh32[r1w + w];
            ah[2] = qh32[r0w + w + 4]; ah[3] = qh32[r1w + w + 4];
#pragma unroll
            for (int nt = 0; nt < 8; nt++) {
                const int nw = (nt * 8 + gid) * (FPAD/2);
                uint32_t bh2[2] = { kh32[nw + w], kh32[nw + w + 4] };
                mma_bf16(sc[nt], ah, bh2);
            }
        }

        __syncthreads();
        issueK(jn); CP_COMMIT();

#pragma unroll
        for (int nt = 0; nt < 8; nt++) {
            const int jc = j0 + nt * 8 + tig * 2;
            __nv_bfloat162 p0 = *(const __nv_bfloat162*)&PDb[(size_t)s_r0 * J_ + jc];
            __nv_bfloat162 p1 = *(const __nv_bfloat162*)&PDb[(size_t)s_r1 * J_ + jc];
            sc[nt][0] = (jc     <= s_r0 + P_)
                        ? (sc[nt][0] + __bfloat162float(p0.x)) * SCALE_ : -1.0e30f;
            sc[nt][1] = (jc + 1 <= s_r0 + P_)
                        ? (sc[nt][1] + __bfloat162float(p0.y)) * SCALE_ : -1.0e30f;
            sc[nt][2] = (jc     <= s_r1 + P_)
                        ? (sc[nt][2] + __bfloat162float(p1.x)) * SCALE_ : -1.0e30f;
            sc[nt][3] = (jc + 1 <= s_r1 + P_)
                        ? (sc[nt][3] + __bfloat162float(p1.y)) * SCALE_ : -1.0e30f;
        }

#pragma unroll
        for (int h = 0; h < 2; h++) {
            float mx = -3.0e38f;
#pragma unroll
            for (int nt = 0; nt < 8; nt++)
                mx = fmaxf(mx, fmaxf(sc[nt][2*h], sc[nt][2*h+1]));
            mx = fmaxf(mx, __shfl_xor_sync(0xffffffffu, mx, 1));
            mx = fmaxf(mx, __shfl_xor_sync(0xffffffffu, mx, 2));
            const float m_new = fmaxf(m_[h], mx);
            const float corr  = __expf(m_[h] - m_new);
            float sum = 0.f;
#pragma unroll
            for (int nt = 0; nt < 8; nt++) {
                float p0 = __expf(sc[nt][2*h]   - m_new);
                float p1 = __expf(sc[nt][2*h+1] - m_new);
                sc[nt][2*h] = p0; sc[nt][2*h+1] = p1;
                sum += p0 + p1;
            }
            sum += __shfl_xor_sync(0xffffffffu, sum, 1);
            sum += __shfl_xor_sync(0xffffffffu, sum, 2);
            l_[h] = l_[h] * corr + sum;
            m_[h] = m_new;
#pragma unroll
            for (int nt = 0; nt < 8; nt++) {
                o[nt][2*h]   *= corr;
                o[nt][2*h+1] *= corr;
            }
        }

        CP_WAIT1();
        __syncthreads();

        const uint32_t* vh32 = (const uint32_t*)sVh;
        const uint32_t* vl32 = (const uint32_t*)sVl;
#pragma unroll
        for (int ks = 0; ks < 4; ks++) {
            uint32_t ph[4], pl[4];
            split2(sc[2*ks][0],   sc[2*ks][1],   ph[0], pl[0]);
            split2(sc[2*ks][2],   sc[2*ks][3],   ph[1], pl[1]);
            split2(sc[2*ks+1][0], sc[2*ks+1][1], ph[2], pl[2]);
            split2(sc[2*ks+1][2], sc[2*ks+1][3], ph[3], pl[3]);
            const int w = ks * 8 + tig;
#pragma unroll
            for (int nt = 0; nt < 8; nt++) {
                const int nw = (nt * 8 + gid) * (FPAD/2);
                uint32_t bh2[2] = { vh32[nw + w], vh32[nw + w + 4] };
                uint32_t bl2[2] = { vl32[nw + w], vl32[nw + w + 4] };
                mma_bf16(o[nt], ph, bh2);
                mma_bf16(o[nt], ph, bl2);
                mma_bf16(o[nt], pl, bh2);
            }
        }

        __syncthreads();
        issueV(jn); CP_COMMIT();
    }
    CP_WAIT0();

    // ---- epilogue: ctx hi/lo bf16, [(s,b)][h*64+i] ----
    const float inv0 = 1.f / l_[0];
    const float inv1 = 1.f / l_[1];
    const int b = bh >> 4, hh = bh & 15;
#pragma unroll
    for (int nt = 0; nt < 8; nt++) {
        const int ic = hh * 64 + nt * 8 + tig * 2;
        float a0 = o[nt][0] * inv0, a1 = o[nt][1] * inv0;
        float b0 = o[nt][2] * inv1, b1 = o[nt][3] * inv1;
        __nv_bfloat16 h0, l0, h1, l1;
        split1(a0, h0, l0); split1(a1, h1, l1);
        size_t o0 = ((size_t)(s_r0 * B_ + b)) * HI_ + ic;
        *(uint32_t*)&g_ctxh[o0] = pack2h(h0, h1);
        *(uint32_t*)&g_ctxl[o0] = pack2h(l0, l1);
        split1(b0, h0, l0); split1(b1, h1, l1);
        size_t o1 = ((size_t)(s_r1 * B_ + b)) * HI_ + ic;
        *(uint32_t*)&g_ctxh[o1] = pack2h(h0, h1);
        *(uint32_t*)&g_ctxl[o1] = pack2h(l0, l1);
    }
}

// ------------------------------ layernorm ----------------------------------
__device__ __forceinline__ float warp_red_sum(float v) {
#pragma unroll
    for (int o = 16; o; o >>= 1) v += __shfl_xor_sync(0xffffffffu, v, o);
    return v;
}
__global__ void __launch_bounds__(256)
ln_kernel(const float* __restrict__ gamma, const float* __restrict__ beta,
          float* __restrict__ out) {
    const int row = blockIdx.x;
    const int tid = threadIdx.x;
    const float* p = g_proj + (size_t)row * E_;
    __shared__ float red[8];

    float v[4];
    float s = 0.f;
#pragma unroll
    for (int t = 0; t < 4; t++) { v[t] = p[tid + t*256]; s += v[t]; }
    s = warp_red_sum(s);
    if ((tid & 31) == 0) red[tid >> 5] = s;
    __syncthreads();
    float tot = 0.f;
#pragma unroll
    for (int w = 0; w < 8; w++) tot += red[w];
    const float mu = tot * (1.0f / E_);

    float vs = 0.f;
#pragma unroll
    for (int t = 0; t < 4; t++) { float d = v[t] - mu; vs += d * d; }
    vs = warp_red_sum(vs);
    __syncthreads();
    if ((tid & 31) == 0) red[tid >> 5] = vs;
    __syncthreads();
    float vtot = 0.f;
#pragma unroll
    for (int w = 0; w < 8; w++) vtot += red[w];
    const float inv = rsqrtf(vtot * (1.0f / E_) + EPS_);

#pragma unroll
    for (int t = 0; t < 4; t++) {
        int e = tid + t*256;
        out[(size_t)row * E_ + e] = (v[t] - mu) * inv * gamma[e] + beta[e];
    }
}

// ------------------------------- launch ------------------------------------
extern "C" void kernel_launch(void* const* d_in, const int* in_sizes, int n_in,
                              void* d_out, int out_size) {
    (void)in_sizes; (void)n_in; (void)out_size;
    const float* x     = (const float*)d_in[0];
    const float* rel   = (const float*)d_in[1];
    const float* mem   = (const float*)d_in[2];
    const float* u     = (const float*)d_in[3];
    const float* v     = (const float*)d_in[4];
    const float* Wkv   = (const float*)d_in[6];
    const float* Wq    = (const float*)d_in[7];
    const float* Wp    = (const float*)d_in[8];
    const float* Wo    = (const float*)d_in[9];
    const float* gamma = (const float*)d_in[10];
    const float* beta  = (const float*)d_in[11];
    float* out = (float*)d_out;

    __nv_bfloat16 *iwh, *iwl, *relh, *wkh, *wvh, *wvl, *wqh, *wph, *woh, *wol;
    cudaGetSymbolAddress((void**)&iwh,  g_iwh);
    cudaGetSymbolAddress((void**)&iwl,  g_iwl);
    cudaGetSymbolAddress((void**)&relh, g_relh);
    cudaGetSymbolAddress((void**)&wkh,  g_wkh);
    cudaGetSymbolAddress((void**)&wvh,  g_wvh);
    cudaGetSymbolAddress((void**)&wvl,  g_wvl);
    cudaGetSymbolAddress((void**)&wqh,  g_wqh);
    cudaGetSymbolAddress((void**)&wph,  g_wph);
    cudaGetSymbolAddress((void**)&woh,  g_woh);
    cudaGetSymbolAddress((void**)&wol,  g_wol);
    __nv_bfloat16 *ctxh, *ctxl;
    cudaGetSymbolAddress((void**)&ctxh, g_ctxh);
    cudaGetSymbolAddress((void**)&ctxl, g_ctxl);

    // attribute calls unconditional; capture-safe
    cudaFuncSetAttribute(flash_mma,
                         cudaFuncAttributeMaxDynamicSharedMemorySize, FLASH_SMEM);
    cudaFuncSetAttribute(pd_kernel,
                         cudaFuncAttributeMaxDynamicSharedMemorySize, PD_SMEM);
    cudaFuncSetAttribute(gemm_bf<false, CStoreK>,
                         cudaFuncAttributeMaxDynamicSharedMemorySize, gemm_smem<false>());
    cudaFuncSetAttribute(gemm_bf<true, CStoreV>,
                         cudaFuncAttributeMaxDynamicSharedMemorySize, gemm_smem<true>());
    cudaFuncSetAttribute(gemm_bf<false, CStoreQ>,
                         cudaFuncAttributeMaxDynamicSharedMemorySize, gemm_smem<false>());
    cudaFuncSetAttribute(gemm_bf<false, CStorePos>,
                         cudaFuncAttributeMaxDynamicSharedMemorySize, gemm_smem<false>());
    cudaFuncSetAttribute(gemm_bf<true, CStoreProj>,
                         cudaFuncAttributeMaxDynamicSharedMemorySize, gemm_smem<true>());

    // 0. operand conversion prepass
    const int PBE = P_ * B_ * E_;
    const int SBE = S_ * B_ * E_;
    conv_hilo<<<(PBE/4 + 255)/256, 256>>>(mem, iwh, iwl, PBE/4);
    conv_hilo<<<(SBE/4 + 255)/256, 256>>>(x, iwh + PBE, iwl + PBE, SBE/4);
    conv_hi  <<<(J_*E_/4 + 255)/256, 256>>>(rel, relh, J_*E_/4);
    conv_hi  <<<(HI_*E_/4 + 255)/256, 256>>>(Wkv, wkh, HI_*E_/4);
    conv_hilo<<<(HI_*E_/4 + 255)/256, 256>>>(Wkv + (size_t)HI_*E_, wvh, wvl, HI_*E_/4);
    conv_hi  <<<(HI_*E_/4 + 255)/256, 256>>>(Wq, wqh, HI_*E_/4);
    conv_hi  <<<(HI_*E_/4 + 255)/256, 256>>>(Wp, wph, HI_*E_/4);
    conv_hilo<<<(E_*HI_/4 + 255)/256, 256>>>(Wo, woh, wol, E_*HI_/4);

    // 1a. K projection (1-term)
    gemm_bf<false><<<dim3(HI_/128, JB_/128), 256, gemm_smem<false>()>>>(
        iwh, nullptr, wkh, nullptr, CStoreK{}, E_);

    // 1b. V projection (3-term)
    gemm_bf<true><<<dim3(HI_/128, JB_/128), 256, gemm_smem<true>()>>>(
        iwh, iwl, wvh, wvl, CStoreV{}, E_);

    // 2. q projection (1-term); A = x rows of iw
    gemm_bf<false><<<dim3(HI_/128, S_*B_/128), 256, gemm_smem<false>()>>>(
        iwh + PBE, nullptr, wqh, nullptr, CStoreQ{u, v}, E_);

    // 3. pos projection (1-term)
    gemm_bf<false><<<dim3(HI_/128, J_/128), 256, gemm_smem<false>()>>>(
        relh, nullptr, wph, nullptr, CStorePos{}, E_);

    // 4. PD
    pd_kernel<<<dim3(J_/256, S_/128, B_*H_), 256, PD_SMEM>>>();

    // 5. flash attention -> ctx hi/lo
    flash_mma<<<dim3(S_/128, B_*H_), 256, FLASH_SMEM>>>();

    // 6. out projection + residual (3-term)
    gemm_bf<true><<<dim3(E_/128, S_*B_/128), 256, gemm_smem<true>()>>>(
        ctxh, ctxl, woh, wol, CStoreProj{x}, HI_);

    // 7. layernorm
    ln_kernel<<<S_*B_, 256>>>(gamma, beta, out);
}

// round 17
// speedup vs baseline: 1.0443x; 1.0443x over previous
#include <cuda_runtime.h>
#include <cuda_bf16.h>
#include <cstdint>

// ---------------------------------------------------------------------------
// Transformer-XL masked MHA. S=1024, P=1024, J=2048, B=2, E=1024, H=16, I=64.
// Operands pre-converted to bf16 in ONE fused prepass; the three 1-term
// projection GEMMs (K, q, pos) are merged into ONE launch to fill the chip.
// Output-side (V-proj, PV, out-proj) stay 3-term split-bf16 (fp32-grade).
// ---------------------------------------------------------------------------

constexpr int S_   = 1024;
constexpr int P_   = 1024;
constexpr int B_   = 2;
constexpr int E_   = 1024;
constexpr int H_   = 16;
constexpr int I_   = 64;
constexpr int J_   = 2048;
constexpr int HI_  = 1024;
constexpr int JB_  = J_ * B_;
constexpr float SCALE_ = 0.125f;
constexpr float EPS_   = 1e-5f;

// ------------------------- scratch (device globals) ------------------------
__device__ __nv_bfloat16 g_iwh [(size_t)JB_*E_];       // concat(mem,x) hi
__device__ __nv_bfloat16 g_iwl [(size_t)JB_*E_];       // concat(mem,x) lo
__device__ __nv_bfloat16 g_relh[(size_t)J_*E_];
__device__ __nv_bfloat16 g_wkh [(size_t)HI_*E_];
__device__ __nv_bfloat16 g_wvh [(size_t)HI_*E_];
__device__ __nv_bfloat16 g_wvl [(size_t)HI_*E_];
__device__ __nv_bfloat16 g_wqh [(size_t)HI_*E_];
__device__ __nv_bfloat16 g_wph [(size_t)HI_*E_];
__device__ __nv_bfloat16 g_woh [(size_t)E_*HI_];
__device__ __nv_bfloat16 g_wol [(size_t)E_*HI_];

__device__ __nv_bfloat16 g_Khi [(size_t)B_*H_*J_*I_];  // [bh][j][i]
__device__ __nv_bfloat16 g_Vthi[(size_t)B_*H_*I_*J_];  // [bh][i][j]
__device__ __nv_bfloat16 g_Vtlo[(size_t)B_*H_*I_*J_];
__device__ __nv_bfloat16 g_quhi[(size_t)B_*H_*S_*I_];
__device__ __nv_bfloat16 g_qvh [(size_t)B_*H_*S_*I_];
__device__ __nv_bfloat16 g_posh[(size_t)H_*J_*I_];
__device__ __nv_bfloat16 g_PD  [(size_t)B_*H_*S_*J_];  // pre-shifted
__device__ __nv_bfloat16 g_ctxh[(size_t)S_*B_*HI_];
__device__ __nv_bfloat16 g_ctxl[(size_t)S_*B_*HI_];
__device__ float g_proj[(size_t)S_*B_*E_];

// ------------------------------ helpers ------------------------------------
__device__ __forceinline__ void split1(float x, __nv_bfloat16& h, __nv_bfloat16& l) {
    h = __float2bfloat16(x);
    l = __float2bfloat16(x - __bfloat162float(h));
}
__device__ __forceinline__ void split2(float x, float y,
                                       uint32_t& hi, uint32_t& lo) {
    __nv_bfloat162 h = __floats2bfloat162_rn(x, y);
    __nv_bfloat162 l = __floats2bfloat162_rn(x - __bfloat162float(h.x),
                                             y - __bfloat162float(h.y));
    hi = *(const uint32_t*)&h;
    lo = *(const uint32_t*)&l;
}
__device__ __forceinline__ uint32_t packbf2(float x, float y) {
    __nv_bfloat162 t = __floats2bfloat162_rn(x, y);
    return *(const uint32_t*)&t;
}
__device__ __forceinline__ uint32_t pack2h(__nv_bfloat16 a, __nv_bfloat16 b) {
    __nv_bfloat162 t; t.x = a; t.y = b;
    return *(const uint32_t*)&t;
}
__device__ __forceinline__ void mma_bf16(float* d, const uint32_t* a,
                                         const uint32_t* b) {
    asm volatile(
        "mma.sync.aligned.m16n8k16.row.col.f32.bf16.bf16.f32 "
        "{%0,%1,%2,%3}, {%4,%5,%6,%7}, {%8,%9}, {%0,%1,%2,%3};"
        : "+f"(d[0]), "+f"(d[1]), "+f"(d[2]), "+f"(d[3])
        : "r"(a[0]), "r"(a[1]), "r"(a[2]), "r"(a[3]), "r"(b[0]), "r"(b[1]));
}

#define CP_ASYNC16(dst_u32, src_ptr) \
    asm volatile("cp.async.cg.shared.global [%0], [%1], 16;" \
                 :: "r"(dst_u32), "l"(src_ptr) : "memory")
#define CP_COMMIT() asm volatile("cp.async.commit_group;" ::: "memory")
#define CP_WAIT1()  asm volatile("cp.async.wait_group 1;" ::: "memory")
#define CP_WAIT0()  asm volatile("cp.async.wait_group 0;" ::: "memory")

// ---------------------- fused conversion prepass ---------------------------
// Region table (float4 units). Sizes: mem 524288, x 524288, rel 524288,
// Wk 262144, Wv 262144, Wq 262144, Wp 262144, Wo 262144.
//  R0 mem hilo [0,       524288)
//  R1 x   hilo [524288, 1048576)
//  R2 rel hi   [1048576,1572864)
//  R3 Wk  hi   [1572864,1835008)
//  R4 Wv  hilo [1835008,2097152)
//  R5 Wq  hi   [2097152,2359296)
//  R6 Wp  hi   [2359296,2621440)
//  R7 Wo  hilo [2621440,2883584)
constexpr int CV_TOT = 2883584;

__global__ void __launch_bounds__(256)
conv_all(const float* __restrict__ x,   const float* __restrict__ rel,
         const float* __restrict__ mem, const float* __restrict__ Wkv,
         const float* __restrict__ Wq,  const float* __restrict__ Wp,
         const float* __restrict__ Wo) {
    int i = blockIdx.x * 256 + threadIdx.x;
    if (i >= CV_TOT) return;

    const float* src;
    __nv_bfloat16 *dh, *dl = nullptr;
    if (i < 524288)       { src = mem;                     dh = g_iwh;  dl = g_iwl; }
    else if (i < 1048576) { i -= 524288;  src = x;
                            dh = g_iwh + (size_t)P_*B_*E_; dl = g_iwl + (size_t)P_*B_*E_; }
    else if (i < 1572864) { i -= 1048576; src = rel;       dh = g_relh; }
    else if (i < 1835008) { i -= 1572864; src = Wkv;       dh = g_wkh;  }
    else if (i < 2097152) { i -= 1835008; src = Wkv + (size_t)HI_*E_;
                            dh = g_wvh;  dl = g_wvl; }
    else if (i < 2359296) { i -= 2097152; src = Wq;        dh = g_wqh;  }
    else if (i < 2621440) { i -= 2359296; src = Wp;        dh = g_wph;  }
    else                  { i -= 2621440; src = Wo;        dh = g_woh;  dl = g_wol; }

    float4 v = ((const float4*)src)[i];
    if (dl) {
        uint32_t h0, l0, h1, l1;
        split2(v.x, v.y, h0, l0);
        split2(v.z, v.w, h1, l1);
        *(uint2*)&dh[(size_t)i * 4] = make_uint2(h0, h1);
        *(uint2*)&dl[(size_t)i * 4] = make_uint2(l0, l1);
    } else {
        *(uint2*)&dh[(size_t)i * 4] =
            make_uint2(packbf2(v.x, v.y), packbf2(v.z, v.w));
    }
}

// ------------------------------- C functors --------------------------------
struct CStoreV {
    __device__ __forceinline__ void operator()(int m, int n, float c) const {
        int j = m / B_, b = m % B_;
        int hh = n >> 6, i = n & 63;
        __nv_bfloat16 h, l;
        split1(c, h, l);
        size_t o = (((size_t)(b*H_ + hh))*I_ + i)*J_ + j;  // transposed
        g_Vthi[o] = h; g_Vtlo[o] = l;
    }
};
struct CStoreProj {
    const float* x;
    __device__ __forceinline__ void operator()(int m, int n, float c) const {
        g_proj[(size_t)m*E_ + n] = c + x[(size_t)m*E_ + n];
    }
};

// ----------------- merged 1-term GEMM: K-proj + q-proj + pos-proj ----------
// grid (8, 64): by<32 -> K-proj (m = iw rows), by<48 -> q-proj, else pos.
// All share K=E=1024, 128x128 tiles, double-buffered cp.async.
constexpr int GROW = 40;
constexpr int GTS  = 128 * GROW;
constexpr int G1_SMEM = 2 * 2 * GTS * 2;        // 40960 B
constexpr int G3_SMEM = 2 * 4 * GTS * 2;        // 81920 B

__global__ void __launch_bounds__(256)
gemm1t_all(const float* __restrict__ u, const float* __restrict__ v) {
    extern __shared__ __nv_bfloat16 gsm[];

    const int tid  = threadIdx.x;
    const int wid  = tid >> 5;
    const int lane = tid & 31;
    const int gid  = lane >> 2;
    const int tig  = lane & 3;
    const int wm   = wid >> 2;
    const int wn   = wid & 3;
    const int by   = blockIdx.y;
    const int n0   = blockIdx.x * 128;

    int task, m0;
    const __nv_bfloat16 *Ah, *Bh;
    if (by < 32)      { task = 0; m0 = by * 128;        Ah = g_iwh;                       Bh = g_wkh; }
    else if (by < 48) { task = 1; m0 = (by - 32) * 128; Ah = g_iwh + (size_t)P_*B_*E_;    Bh = g_wqh; }
    else              { task = 2; m0 = (by - 48) * 128; Ah = g_relh;                      Bh = g_wph; }

    const int frow = tid >> 1;
    const int fb   = (tid & 1) * 32;
    constexpr int K = E_;

    auto issue = [&](int st, int k0) {
        __nv_bfloat16* buf = gsm + st * 2 * GTS;
        const char* sa = (const char*)(Ah + (size_t)(m0 + frow) * K + k0) + fb;
        uint32_t da = (uint32_t)__cvta_generic_to_shared(&buf[frow * GROW]) + fb;
        CP_ASYNC16(da, sa); CP_ASYNC16(da + 16, sa + 16);
        const char* sb = (const char*)(Bh + (size_t)(n0 + frow) * K + k0) + fb;
        uint32_t db = (uint32_t)__cvta_generic_to_shared(&buf[GTS + frow * GROW]) + fb;
        CP_ASYNC16(db, sb); CP_ASYNC16(db + 16, sb + 16);
    };

    float c[4][4][4];
#pragma unroll
    for (int mt = 0; mt < 4; mt++)
#pragma unroll
        for (int nt = 0; nt < 4; nt++)
#pragma unroll
            for (int r = 0; r < 4; r++) c[mt][nt][r] = 0.f;

    issue(0, 0); CP_COMMIT();
    const int nc = K >> 5;
    for (int ch = 0; ch < nc; ch++) {
        if (ch + 1 < nc) { issue((ch + 1) & 1, (ch + 1) * 32); CP_COMMIT(); CP_WAIT1(); }
        else             { CP_WAIT0(); }
        __syncthreads();

        const __nv_bfloat16* buf = gsm + (ch & 1) * 2 * GTS;
        const __nv_bfloat16* sAh = buf;
        const __nv_bfloat16* sBh = buf + GTS;

#pragma unroll
        for (int ks = 0; ks < 2; ks++) {
            const int kk = ks * 16 + tig * 2;
            uint32_t ah[4][4];
#pragma unroll
            for (int mt = 0; mt < 4; mt++) {
                const int m = wm * 64 + mt * 16 + gid;
                ah[mt][0] = *(const uint32_t*)&sAh[m * GROW + kk];
                ah[mt][1] = *(const uint32_t*)&sAh[(m + 8) * GROW + kk];
                ah[mt][2] = *(const uint32_t*)&sAh[m * GROW + kk + 8];
                ah[mt][3] = *(const uint32_t*)&sAh[(m + 8) * GROW + kk + 8];
            }
#pragma unroll
            for (int nt = 0; nt < 4; nt++) {
                const int n = wn * 32 + nt * 8 + gid;
                uint32_t bh[2];
                bh[0] = *(const uint32_t*)&sBh[n * GROW + kk];
                bh[1] = *(const uint32_t*)&sBh[n * GROW + kk + 8];
#pragma unroll
                for (int mt = 0; mt < 4; mt++)
                    mma_bf16(c[mt][nt], ah[mt], bh);
            }
        }
        __syncthreads();
    }

    // ---- epilogue (task dispatch) ----
#pragma unroll
    for (int mt = 0; mt < 4; mt++) {
        const int gm = m0 + wm * 64 + mt * 16 + gid;
#pragma unroll
        for (int nt = 0; nt < 4; nt++) {
            const int gn = n0 + wn * 32 + nt * 8 + tig * 2;
#pragma unroll
            for (int e = 0; e < 4; e++) {
                const int m = gm + (e >> 1) * 8;
                const int n = gn + (e & 1);
                const float cv = c[mt][nt][e];
                if (task == 0) {
                    int j = m / B_, b = m % B_;
                    g_Khi[(((size_t)(b*H_ + (n >> 6)))*J_ + j)*I_ + (n & 63)] =
                        __float2bfloat16(cv);
                } else if (task == 1) {
                    int s = m / B_, b = m % B_;
                    size_t o = (((size_t)(b*H_ + (n >> 6)))*S_ + s)*I_ + (n & 63);
                    g_quhi[o] = __float2bfloat16(cv + u[n]);
                    g_qvh[o]  = __float2bfloat16(cv + v[n]);
                } else {
                    g_posh[((size_t)(n >> 6)*J_ + m)*I_ + (n & 63)] =
                        __float2bfloat16(cv);
                }
            }
        }
    }
}

// ------------------- 3-term split-bf16 cp.async GEMM -----------------------
template<class CS>
__global__ void __launch_bounds__(256)
gemm3t(const __nv_bfloat16* __restrict__ Ah, const __nv_bfloat16* __restrict__ Al,
       const __nv_bfloat16* __restrict__ Bh, const __nv_bfloat16* __restrict__ Bl,
       CS cstore, int K) {
    extern __shared__ __nv_bfloat16 gsm[];

    const int tid  = threadIdx.x;
    const int wid  = tid >> 5;
    const int lane = tid & 31;
    const int gid  = lane >> 2;
    const int tig  = lane & 3;
    const int wm   = wid >> 2;
    const int wn   = wid & 3;
    const int m0   = blockIdx.y * 128;
    const int n0   = blockIdx.x * 128;

    const int frow = tid >> 1;
    const int fb   = (tid & 1) * 32;

    auto issue = [&](int st, int k0) {
        __nv_bfloat16* buf = gsm + st * 4 * GTS;
        const char* sa = (const char*)(Ah + (size_t)(m0 + frow) * K + k0) + fb;
        uint32_t da = (uint32_t)__cvta_generic_to_shared(&buf[frow * GROW]) + fb;
        CP_ASYNC16(da, sa); CP_ASYNC16(da + 16, sa + 16);
        const char* sal = (const char*)(Al + (size_t)(m0 + frow) * K + k0) + fb;
        uint32_t dal = (uint32_t)__cvta_generic_to_shared(&buf[GTS + frow * GROW]) + fb;
        CP_ASYNC16(dal, sal); CP_ASYNC16(dal + 16, sal + 16);
        const char* sb = (const char*)(Bh + (size_t)(n0 + frow) * K + k0) + fb;
        uint32_t db = (uint32_t)__cvta_generic_to_shared(&buf[2 * GTS + frow * GROW]) + fb;
        CP_ASYNC16(db, sb); CP_ASYNC16(db + 16, sb + 16);
        const char* sbl = (const char*)(Bl + (size_t)(n0 + frow) * K + k0) + fb;
        uint32_t dbl = (uint32_t)__cvta_generic_to_shared(&buf[3 * GTS + frow * GROW]) + fb;
        CP_ASYNC16(dbl, sbl); CP_ASYNC16(dbl + 16, sbl + 16);
    };

    float c[4][4][4];
#pragma unroll
    for (int mt = 0; mt < 4; mt++)
#pragma unroll
        for (int nt = 0; nt < 4; nt++)
#pragma unroll
            for (int r = 0; r < 4; r++) c[mt][nt][r] = 0.f;

    issue(0, 0); CP_COMMIT();
    const int nc = K >> 5;
    for (int ch = 0; ch < nc; ch++) {
        if (ch + 1 < nc) { issue((ch + 1) & 1, (ch + 1) * 32); CP_COMMIT(); CP_WAIT1(); }
        else             { CP_WAIT0(); }
        __syncthreads();

        const __nv_bfloat16* buf = gsm + (ch & 1) * 4 * GTS;
        const __nv_bfloat16* sAh = buf;
        const __nv_bfloat16* sAl = buf + GTS;
        const __nv_bfloat16* sBh = buf + 2 * GTS;
        const __nv_bfloat16* sBl = buf + 3 * GTS;

#pragma unroll
        for (int ks = 0; ks < 2; ks++) {
            const int kk = ks * 16 + tig * 2;
            uint32_t ah[4][4], al[4][4];
#pragma unroll
            for (int mt = 0; mt < 4; mt++) {
                const int m = wm * 64 + mt * 16 + gid;
                ah[mt][0] = *(const uint32_t*)&sAh[m * GROW + kk];
                ah[mt][1] = *(const uint32_t*)&sAh[(m + 8) * GROW + kk];
                ah[mt][2] = *(const uint32_t*)&sAh[m * GROW + kk + 8];
                ah[mt][3] = *(const uint32_t*)&sAh[(m + 8) * GROW + kk + 8];
                al[mt][0] = *(const uint32_t*)&sAl[m * GROW + kk];
                al[mt][1] = *(const uint32_t*)&sAl[(m + 8) * GROW + kk];
                al[mt][2] = *(const uint32_t*)&sAl[m * GROW + kk + 8];
                al[mt][3] = *(const uint32_t*)&sAl[(m + 8) * GROW + kk + 8];
            }
#pragma unroll
            for (int nt = 0; nt < 4; nt++) {
                const int n = wn * 32 + nt * 8 + gid;
                uint32_t bh[2], bl[2];
                bh[0] = *(const uint32_t*)&sBh[n * GROW + kk];
                bh[1] = *(const uint32_t*)&sBh[n * GROW + kk + 8];
                bl[0] = *(const uint32_t*)&sBl[n * GROW + kk];
                bl[1] = *(const uint32_t*)&sBl[n * GROW + kk + 8];
#pragma unroll
                for (int mt = 0; mt < 4; mt++) {
                    mma_bf16(c[mt][nt], ah[mt], bh);
                    mma_bf16(c[mt][nt], ah[mt], bl);
                    mma_bf16(c[mt][nt], al[mt], bh);
                }
            }
        }
        __syncthreads();
    }

#pragma unroll
    for (int mt = 0; mt < 4; mt++) {
        const int gm = m0 + wm * 64 + mt * 16 + gid;
#pragma unroll
        for (int nt = 0; nt < 4; nt++) {
            const int gn = n0 + wn * 32 + nt * 8 + tig * 2;
            cstore(gm,     gn,     c[mt][nt][0]);
            cstore(gm,     gn + 1, c[mt][nt][1]);
            cstore(gm + 8, gn,     c[mt][nt][2]);
            cstore(gm + 8, gn + 1, c[mt][nt][3]);
        }
    }
}

// ----------------------- PD kernel (pure bf16, K=64) -----------------------
constexpr int PDW = 36;
constexpr int PD_SMEM = (128 + 64 + 64 + 128) * 72 * 2;   // 55296 B

__global__ void __launch_bounds__(256) pd_kernel() {
    extern __shared__ __nv_bfloat16 psm[];
    __nv_bfloat16* sA   = psm;                // [128][72]
    __nv_bfloat16* sB0  = sA  + 128 * 72;     // [64][72]
    __nv_bfloat16* sB1  = sB0 + 64 * 72;
    __nv_bfloat16* sOut = sB1 + 64 * 72;      // [128][72]

    const int tid  = threadIdx.x;
    const int wq   = tid >> 5;
    const int lane = tid & 31;
    const int gid  = lane >> 2;
    const int tig  = lane & 3;
    const int m0   = blockIdx.y * 128;
    const int ng   = blockIdx.x * 256;
    const int bh   = blockIdx.z;

    int need = 833 - m0 - ng;
    int ns_min = (need <= 0) ? 0 : ((need + 63) >> 6);
    if (ns_min > 3) return;

    const int arow = tid >> 1;
    const int aw   = (tid & 1) * 16;
    const int brow = tid >> 2;
    const int bw   = (tid & 3) * 8;

    auto issueA = [&]() {
        const char* src = (const char*)((const uint32_t*)
            (g_qvh + ((size_t)bh * S_ + m0 + arow) * I_) + aw);
        uint32_t dst = (uint32_t)__cvta_generic_to_shared(
            (uint32_t*)&sA[arow * 72] + aw);
        CP_ASYNC16(dst,      src);
        CP_ASYNC16(dst + 16, src + 16);
        CP_ASYNC16(dst + 32, src + 32);
        CP_ASYNC16(dst + 48, src + 48);
    };
    auto issueB = [&](int ns, __nv_bfloat16* buf) {
        const int n0 = ng + ns * 64;
        const char* src = (const char*)((const uint32_t*)
            (g_posh + ((size_t)(bh & 15) * J_ + n0 + brow) * I_) + bw);
        uint32_t dst = (uint32_t)__cvta_generic_to_shared(
            (uint32_t*)&buf[brow * 72] + bw);
        CP_ASYNC16(dst,      src);
        CP_ASYNC16(dst + 16, src + 16);
    };

    issueA();
    issueB(ns_min, sB0);
    CP_COMMIT();
    if (ns_min + 1 <= 3) { issueB(ns_min + 1, sB1); CP_COMMIT(); }

    const int r0w = (wq * 16 + gid) * PDW;

    for (int ns = ns_min; ns <= 3; ns++) {
        const int idx = ns - ns_min;
        if (ns + 1 <= 3) CP_WAIT1(); else CP_WAIT0();
        __syncthreads();

        const uint32_t* qa = (const uint32_t*)sA;
        const uint32_t* qb = (const uint32_t*)((idx & 1) ? sB1 : sB0);

        float c[8][4];
#pragma unroll
        for (int nt = 0; nt < 8; nt++)
#pragma unroll
            for (int r = 0; r < 4; r++) c[nt][r] = 0.f;

#pragma unroll
        for (int ks = 0; ks < 4; ks++) {
            const int w = ks * 8 + tig;
            uint32_t a[4];
            a[0] = qa[r0w + w];
            a[1] = qa[r0w + 8 * PDW + w];
            a[2] = qa[r0w + w + 4];
            a[3] = qa[r0w + 8 * PDW + w + 4];
#pragma unroll
            for (int nt = 0; nt < 8; nt++) {
                const int nw = (nt * 8 + gid) * PDW;
                uint32_t b2[2] = { qb[nw + w], qb[nw + w + 4] };
                mma_bf16(c[nt], a, b2);
            }
        }
        __syncthreads();
        if (ns + 2 <= 3) { issueB(ns + 2, (idx & 1) ? sB1 : sB0); CP_COMMIT(); }

        {
            const int r0s = (wq * 16 + gid) * 72;
#pragma unroll
            for (int nt = 0; nt < 8; nt++) {
                *(uint32_t*)&sOut[r0s + nt * 8 + tig * 2] =
                    packbf2(c[nt][0], c[nt][1]);
                *(uint32_t*)&sOut[r0s + 8 * 72 + nt * 8 + tig * 2] =
                    packbf2(c[nt][2], c[nt][3]);
            }
        }
        __syncwarp();

        const int n0s = ng + ns * 64;
#pragma unroll
        for (int it = 0; it < 16; it++) {
            const int r  = wq * 16 + it;
            const int gm = m0 + r;
            const int jr = n0s + gm - 1023;
            if (jr + 63 < 0) continue;
            const uint32_t* srow = (const uint32_t*)&sOut[r * 72];
            __nv_bfloat16* drow = g_PD + ((size_t)bh * S_ + gm) * J_;
            if ((jr & 1) == 0) {
                const int j = jr + lane * 2;
                if (j >= 0) *(uint32_t*)&drow[j] = srow[lane];
            } else {
                if (lane < 31) {
                    const int j = jr + 1 + lane * 2;
                    if (j >= 0) {
                        uint32_t w0 = srow[lane], w1 = srow[lane + 1];
                        *(uint32_t*)&drow[j] = (w0 >> 16) | (w1 << 16);
                    }
                } else {
                    if (jr >= 0)      drow[jr]      = sOut[r * 72];
                    if (jr + 63 >= 0) drow[jr + 63] = sOut[r * 72 + 63];
                }
            }
        }
    }
}

// ---------------------------- flash attention (MMA) ------------------------
constexpr int FPAD = 72;
constexpr int FLASH_SMEM = (128 + 64 + 128) * FPAD * 2;  // 46080 B

__global__ void __launch_bounds__(256) flash_mma() {
    extern __shared__ __nv_bfloat16 fsm[];
    __nv_bfloat16* sQh = fsm;                    // [s][i] 128x72
    __nv_bfloat16* sKh = sQh + 128 * FPAD;       // [j][i] 64x72
    __nv_bfloat16* sVh = sKh + 64 * FPAD;        // [i][j] 64x72
    __nv_bfloat16* sVl = sVh + 64 * FPAD;

    const int tid  = threadIdx.x;
    const int wq   = tid >> 5;
    const int lane = tid & 31;
    const int gid  = lane >> 2;
    const int tig  = lane & 3;
    const int s0   = (gridDim.x - 1 - blockIdx.x) * 128;
    const int bh   = blockIdx.y;

    const int s_r0 = s0 + wq * 16 + gid;
    const int s_r1 = s_r0 + 8;

    const int row4 = tid >> 2;
    const int qw   = (tid & 3) * 8;

    auto issueK = [&](int j0) {
        const char* srch = (const char*)((const uint32_t*)
            (g_Khi + (((size_t)bh * J_) + j0 + row4) * I_) + qw);
        uint32_t dh = (uint32_t)__cvta_generic_to_shared(
            (uint32_t*)&sKh[row4 * FPAD] + qw);
        CP_ASYNC16(dh,      srch);
        CP_ASYNC16(dh + 16, srch + 16);
    };
    auto issueV = [&](int j0) {
        const char* srch = (const char*)((const uint32_t*)
            (g_Vthi + ((size_t)bh * I_ + row4) * J_ + j0) + qw);
        const char* srcl = (const char*)((const uint32_t*)
            (g_Vtlo + ((size_t)bh * I_ + row4) * J_ + j0) + qw);
        uint32_t dh = (uint32_t)__cvta_generic_to_shared(
            (uint32_t*)&sVh[row4 * FPAD] + qw);
        uint32_t dl = (uint32_t)__cvta_generic_to_shared(
            (uint32_t*)&sVl[row4 * FPAD] + qw);
        CP_ASYNC16(dh,      srch);
        CP_ASYNC16(dh + 16, srch + 16);
        CP_ASYNC16(dl,      srcl);
        CP_ASYNC16(dl + 16, srcl + 16);
    };

    issueK(0); CP_COMMIT();
    issueV(0); CP_COMMIT();

    {
        const int row  = tid >> 1;
        const int half = (tid & 1) * 16;
        const uint4* srch = (const uint4*)((const uint32_t*)
            (g_quhi + ((size_t)bh * S_ + s0 + row) * I_) + half);
        uint4* dsth = (uint4*)((uint32_t*)&sQh[row * FPAD] + half);
#pragma unroll
        for (int q = 0; q < 4; q++) dsth[q] = srch[q];
    }

    const __nv_bfloat16* PDb = g_PD + (size_t)bh * S_ * J_;

    float m_[2] = {-3.0e38f, -3.0e38f};
    float l_[2] = {0.f, 0.f};
    float o[8][4];
#pragma unroll
    for (int nt = 0; nt < 8; nt++)
#pragma unroll
        for (int r = 0; r < 4; r++) o[nt][r] = 0.f;

    const int ntiles = min(32, s0 / 64 + 18);
    for (int jt = 0; jt < ntiles; jt++) {
        const int j0 = jt * 64;
        const int jn = min(jt + 1, ntiles - 1) * 64;

        CP_WAIT1();
        __syncthreads();

        float sc[8][4];
#pragma unroll
        for (int nt = 0; nt < 8; nt++)
#pragma unroll
            for (int r = 0; r < 4; r++) sc[nt][r] = 0.f;

        const uint32_t* qh32 = (const uint32_t*)sQh;
        const uint32_t* kh32 = (const uint32_t*)sKh;
        const int r0w = (wq * 16 + gid) * (FPAD/2);
        const int r1w = r0w + 8 * (FPAD/2);
#pragma unroll
        for (int ks = 0; ks < 4; ks++) {
            const int w = ks * 8 + tig;
            uint32_t ah[4];
            ah[0] = qh32[r0w + w];     ah[1] = qh32[r1w + w];
            ah[2] = qh32[r0w + w + 4]; ah[3] = qh32[r1w + w + 4];
#pragma unroll
            for (int nt = 0; nt < 8; nt++) {
                const int nw = (nt * 8 + gid) * (FPAD/2);
                uint32_t bh2[2] = { kh32[nw + w], kh32[nw + w + 4] };
                mma_bf16(sc[nt], ah, bh2);
            }
        }

        __syncthreads();
        issueK(jn); CP_COMMIT();

#pragma unroll
        for (int nt = 0; nt < 8; nt++) {
            const int jc = j0 + nt * 8 + tig * 2;
            __nv_bfloat162 p0 = *(const __nv_bfloat162*)&PDb[(size_t)s_r0 * J_ + jc];
            __nv_bfloat162 p1 = *(const __nv_bfloat162*)&PDb[(size_t)s_r1 * J_ + jc];
            sc[nt][0] = (jc     <= s_r0 + P_)
                        ? (sc[nt][0] + __bfloat162float(p0.x)) * SCALE_ : -1.0e30f;
            sc[nt][1] = (jc + 1 <= s_r0 + P_)
                        ? (sc[nt][1] + __bfloat162float(p0.y)) * SCALE_ : -1.0e30f;
            sc[nt][2] = (jc     <= s_r1 + P_)
                        ? (sc[nt][2] + __bfloat162float(p1.x)) * SCALE_ : -1.0e30f;
            sc[nt][3] = (jc + 1 <= s_r1 + P_)
                        ? (sc[nt][3] + __bfloat162float(p1.y)) * SCALE_ : -1.0e30f;
        }

#pragma unroll
        for (int h = 0; h < 2; h++) {
            float mx = -3.0e38f;
#pragma unroll
            for (int nt = 0; nt < 8; nt++)
                mx = fmaxf(mx, fmaxf(sc[nt][2*h], sc[nt][2*h+1]));
            mx = fmaxf(mx, __shfl_xor_sync(0xffffffffu, mx, 1));
            mx = fmaxf(mx, __shfl_xor_sync(0xffffffffu, mx, 2));
            const float m_new = fmaxf(m_[h], mx);
            const float corr  = __expf(m_[h] - m_new);
            float sum = 0.f;
#pragma unroll
            for (int nt = 0; nt < 8; nt++) {
                float p0 = __expf(sc[nt][2*h]   - m_new);
                float p1 = __expf(sc[nt][2*h+1] - m_new);
                sc[nt][2*h] = p0; sc[nt][2*h+1] = p1;
                sum += p0 + p1;
            }
            sum += __shfl_xor_sync(0xffffffffu, sum, 1);
            sum += __shfl_xor_sync(0xffffffffu, sum, 2);
            l_[h] = l_[h] * corr + sum;
            m_[h] = m_new;
#pragma unroll
            for (int nt = 0; nt < 8; nt++) {
                o[nt][2*h]   *= corr;
                o[nt][2*h+1] *= corr;
            }
        }

        CP_WAIT1();
        __syncthreads();

        const uint32_t* vh32 = (const uint32_t*)sVh;
        const uint32_t* vl32 = (const uint32_t*)sVl;
#pragma unroll
        for (int ks = 0; ks < 4; ks++) {
            uint32_t ph[4], pl[4];
            split2(sc[2*ks][0],   sc[2*ks][1],   ph[0], pl[0]);
            split2(sc[2*ks][2],   sc[2*ks][3],   ph[1], pl[1]);
            split2(sc[2*ks+1][0], sc[2*ks+1][1], ph[2], pl[2]);
            split2(sc[2*ks+1][2], sc[2*ks+1][3], ph[3], pl[3]);
            const int w = ks * 8 + tig;
#pragma unroll
            for (int nt = 0; nt < 8; nt++) {
                const int nw = (nt * 8 + gid) * (FPAD/2);
                uint32_t bh2[2] = { vh32[nw + w], vh32[nw + w + 4] };
                uint32_t bl2[2] = { vl32[nw + w], vl32[nw + w + 4] };
                mma_bf16(o[nt], ph, bh2);
                mma_bf16(o[nt], ph, bl2);
                mma_bf16(o[nt], pl, bh2);
            }
        }

        __syncthreads();
        issueV(jn); CP_COMMIT();
    }
    CP_WAIT0();

    const float inv0 = 1.f / l_[0];
    const float inv1 = 1.f / l_[1];
    const int b = bh >> 4, hh = bh & 15;
#pragma unroll
    for (int nt = 0; nt < 8; nt++) {
        const int ic = hh * 64 + nt * 8 + tig * 2;
        float a0 = o[nt][0] * inv0, a1 = o[nt][1] * inv0;
        float b0 = o[nt][2] * inv1, b1 = o[nt][3] * inv1;
        __nv_bfloat16 h0, l0, h1, l1;
        split1(a0, h0, l0); split1(a1, h1, l1);
        size_t o0 = ((size_t)(s_r0 * B_ + b)) * HI_ + ic;
        *(uint32_t*)&g_ctxh[o0] = pack2h(h0, h1);
        *(uint32_t*)&g_ctxl[o0] = pack2h(l0, l1);
        split1(b0, h0, l0); split1(b1, h1, l1);
        size_t o1 = ((size_t)(s_r1 * B_ + b)) * HI_ + ic;
        *(uint32_t*)&g_ctxh[o1] = pack2h(h0, h1);
        *(uint32_t*)&g_ctxl[o1] = pack2h(l0, l1);
    }
}

// ------------------------------ layernorm ----------------------------------
__device__ __forceinline__ float warp_red_sum(float v) {
#pragma unroll
    for (int o = 16; o; o >>= 1) v += __shfl_xor_sync(0xffffffffu, v, o);
    return v;
}
__global__ void __launch_bounds__(256)
ln_kernel(const float* __restrict__ gamma, const float* __restrict__ beta,
          float* __restrict__ out) {
    const int row = blockIdx.x;
    const int tid = threadIdx.x;
    const float* p = g_proj + (size_t)row * E_;
    __shared__ float red[8];

    float v[4];
    float s = 0.f;
#pragma unroll
    for (int t = 0; t < 4; t++) { v[t] = p[tid + t*256]; s += v[t]; }
    s = warp_red_sum(s);
    if ((tid & 31) == 0) red[tid >> 5] = s;
    __syncthreads();
    float tot = 0.f;
#pragma unroll
    for (int w = 0; w < 8; w++) tot += red[w];
    const float mu = tot * (1.0f / E_);

    float vs = 0.f;
#pragma unroll
    for (int t = 0; t < 4; t++) { float d = v[t] - mu; vs += d * d; }
    vs = warp_red_sum(vs);
    __syncthreads();
    if ((tid & 31) == 0) red[tid >> 5] = vs;
    __syncthreads();
    float vtot = 0.f;
#pragma unroll
    for (int w = 0; w < 8; w++) vtot += red[w];
    const float inv = rsqrtf(vtot * (1.0f / E_) + EPS_);

#pragma unroll
    for (int t = 0; t < 4; t++) {
        int e = tid + t*256;
        out[(size_t)row * E_ + e] = (v[t] - mu) * inv * gamma[e] + beta[e];
    }
}

// ------------------------------- launch ------------------------------------
extern "C" void kernel_launch(void* const* d_in, const int* in_sizes, int n_in,
                              void* d_out, int out_size) {
    (void)in_sizes; (void)n_in; (void)out_size;
    const float* x     = (const float*)d_in[0];
    const float* rel   = (const float*)d_in[1];
    const float* mem   = (const float*)d_in[2];
    const float* u     = (const float*)d_in[3];
    const float* v     = (const float*)d_in[4];
    const float* Wkv   = (const float*)d_in[6];
    const float* Wq    = (const float*)d_in[7];
    const float* Wp    = (const float*)d_in[8];
    const float* Wo    = (const float*)d_in[9];
    const float* gamma = (const float*)d_in[10];
    const float* beta  = (const float*)d_in[11];
    float* out = (float*)d_out;

    __nv_bfloat16 *iwh, *iwl, *wvh, *wvl, *woh, *wol, *ctxh, *ctxl;
    cudaGetSymbolAddress((void**)&iwh,  g_iwh);
    cudaGetSymbolAddress((void**)&iwl,  g_iwl);
    cudaGetSymbolAddress((void**)&wvh,  g_wvh);
    cudaGetSymbolAddress((void**)&wvl,  g_wvl);
    cudaGetSymbolAddress((void**)&woh,  g_woh);
    cudaGetSymbolAddress((void**)&wol,  g_wol);
    cudaGetSymbolAddress((void**)&ctxh, g_ctxh);
    cudaGetSymbolAddress((void**)&ctxl, g_ctxl);

    // attribute calls unconditional; capture-safe
    cudaFuncSetAttribute(flash_mma,
                         cudaFuncAttributeMaxDynamicSharedMemorySize, FLASH_SMEM);
    cudaFuncSetAttribute(pd_kernel,
                         cudaFuncAttributeMaxDynamicSharedMemorySize, PD_SMEM);
    cudaFuncSetAttribute(gemm1t_all,
                         cudaFuncAttributeMaxDynamicSharedMemorySize, G1_SMEM);
    cudaFuncSetAttribute(gemm3t<CStoreV>,
                         cudaFuncAttributeMaxDynamicSharedMemorySize, G3_SMEM);
    cudaFuncSetAttribute(gemm3t<CStoreProj>,
                         cudaFuncAttributeMaxDynamicSharedMemorySize, G3_SMEM);

    // 0. fused operand conversion (single launch)
    conv_all<<<(CV_TOT + 255)/256, 256>>>(x, rel, mem, Wkv, Wq, Wp, Wo);

    // 1. merged 1-term projections: K-proj + q-proj + pos-proj (one launch)
    gemm1t_all<<<dim3(HI_/128, 64), 256, G1_SMEM>>>(u, v);

    // 2. V projection (3-term)
    gemm3t<<<dim3(HI_/128, JB_/128), 256, G3_SMEM>>>(
        iwh, iwl, wvh, wvl, CStoreV{}, E_);

    // 3. PD
    pd_kernel<<<dim3(J_/256, S_/128, B_*H_), 256, PD_SMEM>>>();

    // 4. flash attention -> ctx hi/lo
    flash_mma<<<dim3(S_/128, B_*H_), 256, FLASH_SMEM>>>();

    // 5. out projection + residual (3-term)
    gemm3t<<<dim3(E_/128, S_*B_/128), 256, G3_SMEM>>>(
        ctxh, ctxl, woh, wol, CStoreProj{x}, HI_);

    // 6. layernorm
    ln_kernel<<<S_*B_, 256>>>(gamma, beta, out);
}